// round 16
// baseline (speedup 1.0000x reference)
#include <cuda_runtime.h>
#include <cuda_fp16.h>
#include <math.h>
#include <stdint.h>

// ---------------------------------------------------------------------------
// Problem constants
// ---------------------------------------------------------------------------
namespace {
constexpr int nB = 2, nS = 2048, nH = 2048, nNH = 16, nNKV = 4, nDH = 128;
constexpr int nE = 8, nMI = 1408;
constexpr int nT = nB * nS;          // 4096 tokens
constexpr int GR = nT * 2;           // 8192 gathered (token, expert) rows
constexpr int MAXTILE = 72;
constexpr int nQKV = (nNH + 2 * nNKV) * nDH;       // 3072 fused qkv width
constexpr int KOFF = nNH * nDH;                    // 2048
constexpr int VOFF = KOFF + nNKV * nDH;            // 2560
constexpr int nGU = 2 * nMI;                       // 2816 interleaved gate|up
constexpr float RMS_EPS = 1e-6f;
constexpr float QK_SCALE = 0.088388347648318447f;  // 1/sqrt(128)

// GEMM smem (half indices): 3 stages x (A 128x72 + B 128x72)
constexpr int G_HALFS = 55296;
constexpr int SMEM_BYTES = G_HALFS * 2;            // 110592

// flash smem (half indices) — token-major V, 2 CTAs/SM
constexpr int FA_QS = 0;                 // Q  [128][136]
constexpr int FA_KS = 17408;             // K  [64][136]
constexpr int FA_VS = 26112;             // V  2 x [64][136] (token-major)
constexpr int FA_PS = 43520;             // P  [128][72]
constexpr int FA_END = 52736;            // halfs
constexpr int FA_RMf = FA_END / 2;       // float idx: rowmax [128][2]
constexpr int FA_RLf = FA_RMf + 256;     // float idx: rowsum [128][2]
constexpr int FA_BYTES = (FA_RLf + 256) * 4;   // 107520
}

// ---------------------------------------------------------------------------
// Scratch (device globals)
// ---------------------------------------------------------------------------
__device__ __half g_xnh  [(size_t)nT * nH];
__device__ float  g_xf   [(size_t)nT * nH];
__device__ __half g_qkv  [(size_t)nT * nQKV];
__device__ __half g_attn [(size_t)nT * nH];
__device__ float  g_hidden[(size_t)nT * nH];
__device__ __half g_x2h  [(size_t)nT * nH];
__device__ int    g_topi [nT * 2];
__device__ float  g_topw [nT * 2];
__device__ int    g_counts[nE];
__device__ int    g_fill [nE];
__device__ int    g_coff [nE + 1];
__device__ int    g_tileE[MAXTILE];
__device__ int    g_tileR0[MAXTILE];
__device__ int    g_toklist[GR];
__device__ float  g_slotw[GR];
__device__ __half g_ubuf [(size_t)GR * nMI];
// transposed weights [N][K] K-major, fp16
__device__ __half g_wqkvT[(size_t)nQKV * nH];
__device__ __half g_woT [(size_t)nH * nH];
__device__ __half g_guT [(size_t)nE * nGU * nH];
__device__ __half g_dwT [(size_t)nE * nH * nMI];

// ---------------------------------------------------------------------------
// Helpers
// ---------------------------------------------------------------------------
__device__ __forceinline__ uint32_t smem_to_u32(const void* p) {
    uint32_t a;
    asm("{ .reg .u64 t; cvta.to.shared.u64 t, %1; cvt.u32.u64 %0, t; }" : "=r"(a) : "l"(p));
    return a;
}
__device__ __forceinline__ uint32_t pack2h(float x, float y) {
    __half2 h = __floats2half2_rn(x, y);
    return *reinterpret_cast<uint32_t*>(&h);
}
__device__ __forceinline__ void mma_f16(float* d, const uint32_t* a, const uint32_t* b) {
    asm volatile("mma.sync.aligned.m16n8k16.row.col.f32.f16.f16.f32 "
        "{%0,%1,%2,%3}, {%4,%5,%6,%7}, {%8,%9}, {%0,%1,%2,%3};"
        : "+f"(d[0]), "+f"(d[1]), "+f"(d[2]), "+f"(d[3])
        : "r"(a[0]), "r"(a[1]), "r"(a[2]), "r"(a[3]), "r"(b[0]), "r"(b[1]));
}
__device__ __forceinline__ void ldsm4(uint32_t* r, uint32_t addr) {
    asm volatile("ldmatrix.sync.aligned.m8n8.x4.shared.b16 {%0,%1,%2,%3}, [%4];"
        : "=r"(r[0]), "=r"(r[1]), "=r"(r[2]), "=r"(r[3]) : "r"(addr));
}
__device__ __forceinline__ void ldsm4t(uint32_t* r, uint32_t addr) {
    asm volatile("ldmatrix.sync.aligned.m8n8.x4.trans.shared.b16 {%0,%1,%2,%3}, [%4];"
        : "=r"(r[0]), "=r"(r[1]), "=r"(r[2]), "=r"(r[3]) : "r"(addr));
}
__device__ __forceinline__ float warpSum(float v) {
    #pragma unroll
    for (int o = 16; o; o >>= 1) v += __shfl_xor_sync(0xffffffffu, v, o);
    return v;
}
__device__ __forceinline__ float siluf(float x) {
    return x * (1.f / (1.f + expf(-x)));
}

// ---------------------------------------------------------------------------
// fp16 mma GEMM with ldmatrix fragment loads (R12).
// ---------------------------------------------------------------------------
struct GArgs {
    const __half* A; const __half* B;
    float* Cf; __half* Ch;
    const float* resf;
    long long lda, ldb, ldc;
    int M, N, K;
    int mode;     // 0 normal, 1 moe gather-A, 2 moe no-gather
    int outHalf;
    int fuseSilu;
    int scatter;
};

__global__ void __launch_bounds__(256) tc_gemm(GArgs g) {
    extern __shared__ __half gsm[];
    const int tid = threadIdx.x, lane = tid & 31, wid = tid >> 5;
    const int wm = wid & 3, wn = wid >> 2;
    const int gq = lane >> 2, qq = lane & 3;
    const int l15 = lane & 15, lhi = lane >> 4;
    const int blr = (lane & 7) + ((lane >> 4) << 3);
    const int bco = ((lane >> 3) & 1) * 8;

    int m0, Mb;
    const __half* Ab = g.A;
    const __half* Bb = g.B;
    if (g.mode >= 1) {
        int e = g_tileE[blockIdx.y];
        if (e < 0) return;
        m0 = g_tileR0[blockIdx.y];
        Mb = g_coff[e + 1];
        Bb += (size_t)e * g.N * g.K;
    } else {
        m0 = blockIdx.y * 128;
        Mb = g.M;
    }
    const int n0 = blockIdx.x * 128;

    __shared__ int rt[128];
    if (tid < 128) {
        int m = m0 + tid;
        int r = (m < Mb) ? m : -1;
        if (g.mode == 1 && r >= 0) r = g_toklist[r];
        rt[tid] = r;
    }
    __syncthreads();

    const uint32_t sbase = smem_to_u32(gsm);
    const int NC = g.K >> 6;

    auto issue = [&](int c, int s) {
        const int k0 = c << 6;
        const uint32_t ao = (uint32_t)(s * 9216);
        const uint32_t bo = (uint32_t)(27648 + s * 9216);
        #pragma unroll
        for (int p = 0; p < 4; p++) {
            int idx = p * 256 + tid;
            int row = idx >> 3, c8 = idx & 7;
            int r = rt[row];
            const __half* src = (r >= 0 ? Ab + (size_t)r * g.lda : Ab) + k0 + c8 * 8;
            uint32_t dst = sbase + (ao + (uint32_t)(row * 72 + c8 * 8)) * 2u;
            int sz = (r >= 0) ? 16 : 0;
            asm volatile("cp.async.cg.shared.global [%0], [%1], 16, %2;"
                         :: "r"(dst), "l"(src), "r"(sz) : "memory");
        }
        #pragma unroll
        for (int p = 0; p < 4; p++) {
            int idx = p * 256 + tid;
            int row = idx >> 3, c8 = idx & 7;
            const __half* src = Bb + (size_t)(n0 + row) * g.ldb + k0 + c8 * 8;
            uint32_t dst = sbase + (bo + (uint32_t)(row * 72 + c8 * 8)) * 2u;
            asm volatile("cp.async.cg.shared.global [%0], [%1], 16, %2;"
                         :: "r"(dst), "l"(src), "r"(16) : "memory");
        }
    };

    float acc[2][8][4] = {};

    issue(0, 0);
    asm volatile("cp.async.commit_group;" ::: "memory");
    issue(1, 1);
    asm volatile("cp.async.commit_group;" ::: "memory");

    const uint32_t aLane = (uint32_t)((wm * 32 + l15) * 72 + lhi * 8);
    uint32_t bLane[4];
    #pragma unroll
    for (int p = 0; p < 4; p++)
        bLane[p] = (uint32_t)((wn * 64 + p * 16 + blr) * 72 + bco);

    for (int c = 0; c < NC; c++) {
        const int s = c % 3;
        asm volatile("cp.async.wait_group 1;" ::: "memory");
        __syncthreads();
        if (c + 2 < NC) issue(c + 2, (c + 2) % 3);
        asm volatile("cp.async.commit_group;" ::: "memory");

        const uint32_t Aad = sbase + ((uint32_t)(s * 9216) + aLane) * 2u;
        const uint32_t Bad = sbase + (uint32_t)(27648 + s * 9216) * 2u;
        #pragma unroll
        for (int kk = 0; kk < 4; kk++) {
            uint32_t af[2][4], bf[4][4];
            ldsm4(af[0], Aad + kk * 32);
            ldsm4(af[1], Aad + 16 * 144 + kk * 32);
            #pragma unroll
            for (int p = 0; p < 4; p++)
                ldsm4(bf[p], Bad + bLane[p] * 2u + kk * 32);
            #pragma unroll
            for (int mt = 0; mt < 2; mt++)
                #pragma unroll
                for (int p = 0; p < 4; p++) {
                    mma_f16(acc[mt][2 * p],     af[mt], &bf[p][0]);
                    mma_f16(acc[mt][2 * p + 1], af[mt], &bf[p][2]);
                }
        }
    }

    // Epilogue
    #pragma unroll
    for (int mt = 0; mt < 2; mt++) {
        #pragma unroll
        for (int half_ = 0; half_ < 2; half_++) {
            int r = m0 + wm * 32 + mt * 16 + half_ * 8 + gq;
            if (r >= Mb) continue;
            if (g.fuseSilu) {
                #pragma unroll
                for (int nt = 0; nt < 8; nt += 2) {
                    float g0 = acc[mt][nt][half_ * 2 + 0];
                    float g1 = acc[mt][nt][half_ * 2 + 1];
                    float u0 = acc[mt][nt + 1][half_ * 2 + 0];
                    float u1 = acc[mt][nt + 1][half_ * 2 + 1];
                    int cint = n0 + wn * 64 + nt * 8;
                    int L = ((cint) >> 4) * 8 + 2 * qq;
                    *reinterpret_cast<uint32_t*>(g.Ch + (size_t)r * g.ldc + L) =
                        pack2h(siluf(g0) * u0, siluf(g1) * u1);
                }
            } else if (g.scatter) {
                int tok = g_toklist[r];
                float w = g_slotw[r];
                float* orow = g.Cf + (size_t)tok * g.ldc;
                const int cb = n0 + wn * 64 + 2 * qq;
                #pragma unroll
                for (int nt = 0; nt < 8; nt++) {
                    atomicAdd(&orow[cb + nt * 8],     w * acc[mt][nt][half_ * 2 + 0]);
                    atomicAdd(&orow[cb + nt * 8 + 1], w * acc[mt][nt][half_ * 2 + 1]);
                }
            } else {
                const int cb = n0 + wn * 64 + 2 * qq;
                #pragma unroll
                for (int nt = 0; nt < 8; nt++) {
                    float vx = acc[mt][nt][half_ * 2 + 0];
                    float vy = acc[mt][nt][half_ * 2 + 1];
                    int col = cb + nt * 8;
                    if (g.outHalf) {
                        *reinterpret_cast<uint32_t*>(g.Ch + (size_t)r * g.ldc + col) = pack2h(vx, vy);
                    } else {
                        if (g.resf) {
                            float2 rv = *reinterpret_cast<const float2*>(g.resf + (size_t)r * g.ldc + col);
                            vx += rv.x; vy += rv.y;
                        }
                        *reinterpret_cast<float2*>(g.Cf + (size_t)r * g.ldc + col) = make_float2(vx, vy);
                    }
                }
            }
        }
    }
}

// ---------------------------------------------------------------------------
// Fused flash attention — R12 structure, V token-major via ldmatrix.trans.
// ---------------------------------------------------------------------------
__global__ void __launch_bounds__(256) flash_kernel() {
    extern __shared__ __half fh[];
    float* ff = reinterpret_cast<float*>(fh);
    const int tid = threadIdx.x, lane = tid & 31, wid = tid >> 5;
    const int wm = wid & 3, wn = wid >> 2;
    const int gq = lane >> 2, qq = lane & 3;
    const int l15 = lane & 15, lhi = lane >> 4;
    const int blr = (lane & 7) + ((lane >> 4) << 3);       // K (non-trans)
    const int bco = ((lane >> 3) & 1) * 8;
    const int vlr = (lane & 7) + (((lane >> 3) & 1) << 3); // V (trans): token row
    const int vco = (lane >> 4) * 8;                       // V (trans): dh sub-col
    const int bh = blockIdx.y, b = bh >> 4, h = bh & 15, kh = h >> 2;
    const int q0 = blockIdx.x * 128;

    const __half* Qg = g_qkv + ((size_t)(b * nS + q0)) * nQKV + h * nDH;
    const __half* Kg = g_qkv + (size_t)b * nS * nQKV + KOFF + kh * nDH;
    const __half* Vg = g_qkv + (size_t)b * nS * nQKV + VOFF + kh * nDH;
    __half* Og = g_attn + ((size_t)(b * nS + q0)) * nH + h * nDH;

    const uint32_t sb = smem_to_u32(fh);

    #pragma unroll
    for (int p = 0; p < 8; p++) {
        int idx = p * 256 + tid;
        int row = idx >> 4, c8 = idx & 15;
        uint32_t dst = sb + (uint32_t)(FA_QS + row * 136 + c8 * 8) * 2u;
        asm volatile("cp.async.cg.shared.global [%0], [%1], 16;"
                     :: "r"(dst), "l"(Qg + (size_t)row * nQKV + c8 * 8) : "memory");
    }
    asm volatile("cp.async.commit_group;" ::: "memory");

    auto issueKV = [&](int it2) {
        const __half* kg = Kg + (size_t)(it2 * 64) * nQKV;
        const __half* vg = Vg + (size_t)(it2 * 64) * nQKV;
        const int vb = FA_VS + (it2 & 1) * 8704;
        #pragma unroll
        for (int p = 0; p < 4; p++) {
            int idx = p * 256 + tid;
            int row = idx >> 4, c8 = idx & 15;
            uint32_t dk = sb + (uint32_t)(FA_KS + row * 136 + c8 * 8) * 2u;
            asm volatile("cp.async.cg.shared.global [%0], [%1], 16;"
                         :: "r"(dk), "l"(kg + (size_t)row * nQKV + c8 * 8) : "memory");
            uint32_t dv = sb + (uint32_t)(vb + row * 136 + c8 * 8) * 2u;
            asm volatile("cp.async.cg.shared.global [%0], [%1], 16;"
                         :: "r"(dv), "l"(vg + (size_t)row * nQKV + c8 * 8) : "memory");
        }
    };
    issueKV(0);
    asm volatile("cp.async.commit_group;" ::: "memory");

    float accO[2][8][4] = {};
    float rm[2][2] = {{-1e30f, -1e30f}, {-1e30f, -1e30f}};
    float rl[2][2] = {{0.f, 0.f}, {0.f, 0.f}};
    const int PSu = FA_PS / 2;

    const uint32_t QA = sb + (uint32_t)(FA_QS + (wm * 32 + l15) * 136 + lhi * 8) * 2u;
    uint32_t KB[2];
    #pragma unroll
    for (int p = 0; p < 2; p++)
        KB[p] = sb + (uint32_t)(FA_KS + (wn * 32 + p * 16 + blr) * 136 + bco) * 2u;
    const uint32_t PA = sb + (uint32_t)(FA_PS + (wm * 32 + l15) * 72 + lhi * 8) * 2u;
    // V (trans): per-lane base + per-p dh offsets within warp's 64-dh block
    const uint32_t VL = (uint32_t)(vlr * 136 + vco) * 2u;
    uint32_t VBl[4];
    #pragma unroll
    for (int p = 0; p < 4; p++)
        VBl[p] = VL + (uint32_t)(wn * 64 + p * 16) * 2u;

    for (int it = 0; it < nS / 64; it++) {
        asm volatile("cp.async.wait_group 0;" ::: "memory");
        __syncthreads();

        // --- S = Q x K^T ---
        float S[2][4][4] = {};
        #pragma unroll
        for (int kc = 0; kc < 8; kc++) {
            uint32_t af[2][4], bf[2][4];
            ldsm4(af[0], QA + kc * 32);
            ldsm4(af[1], QA + 16 * 272 + kc * 32);
            ldsm4(bf[0], KB[0] + kc * 32);
            ldsm4(bf[1], KB[1] + kc * 32);
            #pragma unroll
            for (int mt = 0; mt < 2; mt++)
                #pragma unroll
                for (int p = 0; p < 2; p++) {
                    mma_f16(S[mt][2 * p],     af[mt], &bf[p][0]);
                    mma_f16(S[mt][2 * p + 1], af[mt], &bf[p][2]);
                }
        }
        __syncthreads();
        if (it + 1 < nS / 64) issueKV(it + 1);
        asm volatile("cp.async.commit_group;" ::: "memory");

        float tmax[2][2] = {{-1e30f, -1e30f}, {-1e30f, -1e30f}};
        #pragma unroll
        for (int mt = 0; mt < 2; mt++)
            #pragma unroll
            for (int nt = 0; nt < 4; nt++)
                #pragma unroll
                for (int c = 0; c < 4; c++) {
                    S[mt][nt][c] *= QK_SCALE;
                    tmax[mt][c >> 1] = fmaxf(tmax[mt][c >> 1], S[mt][nt][c]);
                }
        #pragma unroll
        for (int mt = 0; mt < 2; mt++)
            #pragma unroll
            for (int hf = 0; hf < 2; hf++) {
                float v = tmax[mt][hf];
                v = fmaxf(v, __shfl_xor_sync(0xffffffffu, v, 1));
                v = fmaxf(v, __shfl_xor_sync(0xffffffffu, v, 2));
                tmax[mt][hf] = v;
            }
        if (qq == 0) {
            #pragma unroll
            for (int mt = 0; mt < 2; mt++)
                #pragma unroll
                for (int hf = 0; hf < 2; hf++)
                    ff[FA_RMf + (wm * 32 + mt * 16 + hf * 8 + gq) * 2 + wn] = tmax[mt][hf];
        }
        __syncthreads();

        float newm[2][2], sco[2][2];
        #pragma unroll
        for (int mt = 0; mt < 2; mt++)
            #pragma unroll
            for (int hf = 0; hf < 2; hf++) {
                int r = wm * 32 + mt * 16 + hf * 8 + gq;
                float tm = fmaxf(ff[FA_RMf + r * 2], ff[FA_RMf + r * 2 + 1]);
                float nm = fmaxf(rm[mt][hf], tm);
                sco[mt][hf] = __expf(rm[mt][hf] - nm);
                newm[mt][hf] = nm;
                rm[mt][hf] = nm;
            }

        float ps[2][2] = {{0.f, 0.f}, {0.f, 0.f}};
        uint32_t* Pw = reinterpret_cast<uint32_t*>(fh);
        #pragma unroll
        for (int mt = 0; mt < 2; mt++) {
            int r0 = wm * 32 + mt * 16 + gq;
            #pragma unroll
            for (int nt = 0; nt < 4; nt++) {
                int ci = wn * 16 + nt * 4 + qq;
                float p0 = __expf(S[mt][nt][0] - newm[mt][0]);
                float p1 = __expf(S[mt][nt][1] - newm[mt][0]);
                float p2 = __expf(S[mt][nt][2] - newm[mt][1]);
                float p3 = __expf(S[mt][nt][3] - newm[mt][1]);
                ps[mt][0] += p0 + p1;
                ps[mt][1] += p2 + p3;
                Pw[PSu + r0 * 36 + ci] = pack2h(p0, p1);
                Pw[PSu + (r0 + 8) * 36 + ci] = pack2h(p2, p3);
            }
        }
        #pragma unroll
        for (int mt = 0; mt < 2; mt++)
            #pragma unroll
            for (int hf = 0; hf < 2; hf++) {
                float v = ps[mt][hf];
                v += __shfl_xor_sync(0xffffffffu, v, 1);
                v += __shfl_xor_sync(0xffffffffu, v, 2);
                ps[mt][hf] = v;
            }
        if (qq == 0) {
            #pragma unroll
            for (int mt = 0; mt < 2; mt++)
                #pragma unroll
                for (int hf = 0; hf < 2; hf++)
                    ff[FA_RLf + (wm * 32 + mt * 16 + hf * 8 + gq) * 2 + wn] = ps[mt][hf];
        }
        __syncthreads();

        #pragma unroll
        for (int mt = 0; mt < 2; mt++)
            #pragma unroll
            for (int hf = 0; hf < 2; hf++) {
                int r = wm * 32 + mt * 16 + hf * 8 + gq;
                float ts = ff[FA_RLf + r * 2] + ff[FA_RLf + r * 2 + 1];
                rl[mt][hf] = rl[mt][hf] * sco[mt][hf] + ts;
            }
        #pragma unroll
        for (int mt = 0; mt < 2; mt++)
            #pragma unroll
            for (int nt = 0; nt < 8; nt++) {
                accO[mt][nt][0] *= sco[mt][0];
                accO[mt][nt][1] *= sco[mt][0];
                accO[mt][nt][2] *= sco[mt][1];
                accO[mt][nt][3] *= sco[mt][1];
            }

        // --- O += P x V (V token-major, trans ldmatrix) ---
        const uint32_t Vad = sb + (uint32_t)(FA_VS + (it & 1) * 8704) * 2u;
        #pragma unroll
        for (int kc = 0; kc < 4; kc++) {
            uint32_t af[2][4], bf[4][4];
            ldsm4(af[0], PA + kc * 32);
            ldsm4(af[1], PA + 16 * 144 + kc * 32);
            #pragma unroll
            for (int p = 0; p < 4; p++)
                ldsm4t(bf[p], Vad + kc * 4352 + VBl[p]);
            #pragma unroll
            for (int mt = 0; mt < 2; mt++)
                #pragma unroll
                for (int p = 0; p < 4; p++) {
                    mma_f16(accO[mt][2 * p],     af[mt], &bf[p][0]);
                    mma_f16(accO[mt][2 * p + 1], af[mt], &bf[p][2]);
                }
        }
    }

    #pragma unroll
    for (int mt = 0; mt < 2; mt++)
        #pragma unroll
        for (int hf = 0; hf < 2; hf++) {
            int r = wm * 32 + mt * 16 + hf * 8 + gq;
            float inv = 1.f / rl[mt][hf];
            #pragma unroll
            for (int nt = 0; nt < 8; nt++) {
                int col = wn * 64 + nt * 8 + 2 * qq;
                *reinterpret_cast<uint32_t*>(Og + (size_t)r * nH + col) =
                    pack2h(accO[mt][nt][hf * 2 + 0] * inv, accO[mt][nt][hf * 2 + 1] * inv);
            }
        }
}

// ---------------------------------------------------------------------------
// Weight transpose fp32->fp16, 64k x 128n tile, optional gate/up interleave.
// ---------------------------------------------------------------------------
__global__ void __launch_bounds__(256) transpose_kernel(
    const float* __restrict__ in, __half* __restrict__ out, int K, int N,
    long long srcZ, long long dstZ, int remapOfs) {
    __shared__ float t[64][137];
    const float* ip = in + (size_t)blockIdx.z * srcZ;
    __half* op = out + (size_t)blockIdx.z * dstZ;
    const int n0 = blockIdx.x * 128, k0 = blockIdx.y * 64;
    const int tid = threadIdx.x;
    const int rr = tid >> 5, rc = tid & 31;
    #pragma unroll
    for (int p = 0; p < 8; p++) {
        int kk = rr + p * 8;
        float4 v = *reinterpret_cast<const float4*>(ip + (size_t)(k0 + kk) * N + n0 + rc * 4);
        t[kk][rc * 4 + 0] = v.x; t[kk][rc * 4 + 1] = v.y;
        t[kk][rc * 4 + 2] = v.z; t[kk][rc * 4 + 3] = v.w;
    }
    __syncthreads();
    const int wr = tid >> 3, wk8 = (tid & 7) * 8;
    #pragma unroll
    for (int p = 0; p < 4; p++) {
        int nn = wr + p * 32;
        int ng = n0 + nn;
        int nd = (remapOfs < 0) ? ng : ((ng >> 3) << 4) + (ng & 7) + remapOfs;
        __half hv[8];
        #pragma unroll
        for (int j = 0; j < 8; j++) hv[j] = __float2half_rn(t[wk8 + j][nn]);
        *reinterpret_cast<uint4*>(op + (size_t)nd * K + k0 + wk8) =
            *reinterpret_cast<uint4*>(hv);
    }
}

// ---------------------------------------------------------------------------
// RMSNorm. rmsnorm1 -> half. rmsnorm2 -> half + float (router) + out init.
// ---------------------------------------------------------------------------
template <bool DUAL>
__device__ __forceinline__ void rmsnorm_row(const float* __restrict__ x,
                                            const float* __restrict__ w,
                                            __half* __restrict__ out_h,
                                            float* __restrict__ out_f,
                                            float* __restrict__ out_cp) {
    int row = blockIdx.x;
    const float* xr = x + (size_t)row * nH;
    float ss = 0.f;
    for (int i = threadIdx.x; i < nH; i += blockDim.x) { float v = xr[i]; ss += v * v; }
    __shared__ float sm[8];
    int lane = threadIdx.x & 31, wid = threadIdx.x >> 5;
    ss = warpSum(ss);
    if (lane == 0) sm[wid] = ss;
    __syncthreads();
    if (wid == 0) {
        float v = (lane < 8) ? sm[lane] : 0.f;
        v = warpSum(v);
        if (lane == 0) sm[0] = rsqrtf(v / (float)nH + RMS_EPS);
    }
    __syncthreads();
    float inv = sm[0];
    for (int i = threadIdx.x; i < nH; i += blockDim.x) {
        float xi = xr[i];
        float v = xi * inv * w[i];
        out_h[(size_t)row * nH + i] = __float2half_rn(v);
        if (DUAL) {
            out_f[(size_t)row * nH + i] = v;
            out_cp[(size_t)row * nH + i] = xi;
        }
    }
}
__global__ void rmsnorm1_kernel(const float* __restrict__ hs, const float* __restrict__ w) {
    rmsnorm_row<false>(hs, w, g_xnh, nullptr, nullptr);
}
__global__ void rmsnorm2_kernel(const float* __restrict__ w, float* __restrict__ out) {
    rmsnorm_row<true>(g_hidden, w, g_x2h, g_xf, out);
}

// ---------------------------------------------------------------------------
// RoPE on fused qkv (fp32 math). Only q and k sections.
// ---------------------------------------------------------------------------
__global__ void rope_kernel(const float* __restrict__ cosb, const float* __restrict__ sinb) {
    int i = blockIdx.x * blockDim.x + threadIdx.x;
    if (i >= nT * (nNH + nNKV) * 64) return;
    int d  = i & 63;
    int hh = (i >> 6) % (nNH + nNKV);
    int t  = i / (64 * (nNH + nNKV));
    __half* ptr = g_qkv + (size_t)t * nQKV +
                  (hh < nNH ? hh * nDH : KOFF + (hh - nNH) * nDH);
    float x1 = __half2float(ptr[d]), x2 = __half2float(ptr[d + 64]);
    const float* cr = cosb + (size_t)t * nDH;
    const float* sr = sinb + (size_t)t * nDH;
    ptr[d]      = __float2half_rn(x1 * cr[d]      - x2 * sr[d]);
    ptr[d + 64] = __float2half_rn(x2 * cr[d + 64] + x1 * sr[d + 64]);
}

// ---------------------------------------------------------------------------
// Router (UNROUNDED fp32 input)
// ---------------------------------------------------------------------------
__global__ void router_kernel(const float* __restrict__ rw) {
    __shared__ float xs[nH];
    __shared__ float lg[nE];
    int t = blockIdx.x;
    for (int i = threadIdx.x; i < nH; i += blockDim.x) xs[i] = g_xf[(size_t)t * nH + i];
    __syncthreads();
    int w = threadIdx.x >> 5, lane = threadIdx.x & 31;
    float s = 0.f;
    for (int i = lane; i < nH; i += 32) s += xs[i] * rw[(size_t)i * nE + w];
    s = warpSum(s);
    if (lane == 0) lg[w] = s;
    __syncthreads();
    if (threadIdx.x == 0) {
        float mx = lg[0];
        #pragma unroll
        for (int e = 1; e < nE; e++) mx = fmaxf(mx, lg[e]);
        float p[nE]; float sum = 0.f;
        #pragma unroll
        for (int e = 0; e < nE; e++) { p[e] = expf(lg[e] - mx); sum += p[e]; }
        #pragma unroll
        for (int e = 0; e < nE; e++) p[e] /= sum;
        int i1 = 0;
        #pragma unroll
        for (int e = 1; e < nE; e++) if (p[e] > p[i1]) i1 = e;
        int i2 = (i1 == 0) ? 1 : 0;
        #pragma unroll
        for (int e = 0; e < nE; e++) if (e != i1 && p[e] > p[i2]) i2 = e;
        float s2 = p[i1] + p[i2];
        g_topi[t * 2] = i1; g_topi[t * 2 + 1] = i2;
        g_topw[t * 2] = p[i1] / s2; g_topw[t * 2 + 1] = p[i2] / s2;
    }
}

// ---------------------------------------------------------------------------
// MoE bookkeeping (R12 versions)
// ---------------------------------------------------------------------------
__global__ void reset_kernel() {
    int i = threadIdx.x;
    if (i < nE) { g_counts[i] = 0; g_fill[i] = 0; }
}
__global__ void count_kernel() {
    int t = blockIdx.x * blockDim.x + threadIdx.x;
    if (t >= nT) return;
    atomicAdd(&g_counts[g_topi[t * 2]], 1);
    atomicAdd(&g_counts[g_topi[t * 2 + 1]], 1);
}
__global__ void scan_kernel() {
    if (threadIdx.x != 0) return;
    int off = 0, nt_ = 0;
    for (int e = 0; e < nE; e++) {
        g_coff[e] = off;
        int ne = g_counts[e];
        int ntl = (ne + 127) >> 7;
        for (int i = 0; i < ntl; i++) { g_tileE[nt_] = e; g_tileR0[nt_] = off + i * 128; nt_++; }
        off += ne;
    }
    g_coff[nE] = off;
    for (int i = nt_; i < MAXTILE; i++) g_tileE[i] = -1;
}
__global__ void scatter_kernel() {
    int t = blockIdx.x * blockDim.x + threadIdx.x;
    if (t >= nT) return;
    #pragma unroll
    for (int k = 0; k < 2; k++) {
        int e = g_topi[t * 2 + k];
        int pos = g_coff[e] + atomicAdd(&g_fill[e], 1);
        g_toklist[pos] = t;
        g_slotw[pos] = g_topw[t * 2 + k];
    }
}

// ---------------------------------------------------------------------------
// Launch
// ---------------------------------------------------------------------------
static void launch_gemm(const __half* A, long long lda, const __half* B, long long ldb,
                        float* Cf, __half* Ch, long long ldc, const float* resf,
                        int M, int N, int K, int mode, int outHalf, int fuseSilu,
                        int scatter, dim3 grid) {
    GArgs g;
    g.A = A; g.B = B; g.Cf = Cf; g.Ch = Ch; g.resf = resf;
    g.lda = lda; g.ldb = ldb; g.ldc = ldc;
    g.M = M; g.N = N; g.K = K;
    g.mode = mode; g.outHalf = outHalf; g.fuseSilu = fuseSilu; g.scatter = scatter;
    tc_gemm<<<grid, 256, SMEM_BYTES>>>(g);
}

extern "C" void kernel_launch(void* const* d_in, const int* in_sizes, int n_in,
                              void* d_out, int out_size) {
    const float* hs   = (const float*)d_in[0];
    const float* cosb = (const float*)d_in[1];
    const float* sinb = (const float*)d_in[2];
    const float* wq   = (const float*)d_in[3];
    const float* wk   = (const float*)d_in[4];
    const float* wv   = (const float*)d_in[5];
    const float* wo   = (const float*)d_in[6];
    const float* ln1  = (const float*)d_in[7];
    const float* ln2  = (const float*)d_in[8];
    const float* rw   = (const float*)d_in[9];
    const float* gw   = (const float*)d_in[10];
    const float* uw   = (const float*)d_in[11];
    const float* dw   = (const float*)d_in[12];
    float* out = (float*)d_out;

    static bool attr_set = false;
    if (!attr_set) {
        cudaFuncSetAttribute(tc_gemm, cudaFuncAttributeMaxDynamicSharedMemorySize, SMEM_BYTES);
        cudaFuncSetAttribute(flash_kernel, cudaFuncAttributeMaxDynamicSharedMemorySize, FA_BYTES);
        attr_set = true;
    }

    __half* wqkvT; cudaGetSymbolAddress((void**)&wqkvT, g_wqkvT);
    __half* woT; cudaGetSymbolAddress((void**)&woT, g_woT);
    __half* guT; cudaGetSymbolAddress((void**)&guT, g_guT);
    __half* dwT; cudaGetSymbolAddress((void**)&dwT, g_dwT);
    __half* xnh; cudaGetSymbolAddress((void**)&xnh, g_xnh);
    __half* qkv; cudaGetSymbolAddress((void**)&qkv, g_qkv);
    __half* at;  cudaGetSymbolAddress((void**)&at, g_attn);
    float*  hid; cudaGetSymbolAddress((void**)&hid, g_hidden);
    __half* x2h; cudaGetSymbolAddress((void**)&x2h, g_x2h);
    __half* ub;  cudaGetSymbolAddress((void**)&ub, g_ubuf);

    reset_kernel<<<1, 32>>>();

    // Weight transposes -> [N][K] fp16
    transpose_kernel<<<dim3(16, 32, 1), 256>>>(wq, wqkvT, nH, nNH * nDH, 0, 0, -1);
    transpose_kernel<<<dim3(4, 32, 1), 256>>>(wk, wqkvT + (size_t)KOFF * nH, nH, nNKV * nDH, 0, 0, -1);
    transpose_kernel<<<dim3(4, 32, 1), 256>>>(wv, wqkvT + (size_t)VOFF * nH, nH, nNKV * nDH, 0, 0, -1);
    transpose_kernel<<<dim3(16, 32, 1), 256>>>(wo, woT, nH, nH, 0, 0, -1);
    transpose_kernel<<<dim3(11, 32, nE), 256>>>(gw, guT, nH, nMI,
        (long long)nH * nMI, (long long)nGU * nH, 0);
    transpose_kernel<<<dim3(11, 32, nE), 256>>>(uw, guT, nH, nMI,
        (long long)nH * nMI, (long long)nGU * nH, 8);
    transpose_kernel<<<dim3(16, 22, nE), 256>>>(dw, dwT, nMI, nH,
        (long long)nMI * nH, (long long)nMI * nH, -1);

    rmsnorm1_kernel<<<nT, 256>>>(hs, ln1);

    // Fused QKV projection (half out, N=3072)
    launch_gemm(xnh, nH, wqkvT, nH, nullptr, qkv, nQKV, nullptr,
                nT, nQKV, nH, 0, 1, 0, 0, dim3(24, 32, 1));

    rope_kernel<<<(nT * (nNH + nNKV) * 64) / 256, 256>>>(cosb, sinb);

    // fused attention (V read directly from g_qkv, token-major)
    flash_kernel<<<dim3(nS / 128, nB * nNH), 256, FA_BYTES>>>();

    // hidden = attn @ wo + residual (fp32)
    launch_gemm(at, nH, woT, nH, hid, nullptr, nH, hs,
                nT, nH, nH, 0, 0, 0, 0, dim3(16, 32, 1));

    rmsnorm2_kernel<<<nT, 256>>>(ln2, out);   // also: out = hidden
    router_kernel<<<nT, 256>>>(rw);

    count_kernel<<<nT / 256, 256>>>();
    scan_kernel<<<1, 1>>>();
    scatter_kernel<<<nT / 256, 256>>>();

    // MoE: fused gate+up (interleaved, silu in epilogue) -> ubuf (half)
    launch_gemm(x2h, nH, guT, nH, nullptr, ub, nMI, nullptr,
                GR, nGU, nH, 1, 0, 1, 0, dim3(22, MAXTILE, 1));
    // down: scatter-add into out
    launch_gemm(ub, nMI, dwT, nMI, out, nullptr, nH, nullptr,
                GR, nH, nMI, 2, 0, 0, 1, dim3(16, MAXTILE, 1));
}

// round 17
// speedup vs baseline: 1.0122x; 1.0122x over previous
#include <cuda_runtime.h>
#include <cuda_fp16.h>
#include <math.h>
#include <stdint.h>

// ---------------------------------------------------------------------------
// Problem constants
// ---------------------------------------------------------------------------
namespace {
constexpr int nB = 2, nS = 2048, nH = 2048, nNH = 16, nNKV = 4, nDH = 128;
constexpr int nE = 8, nMI = 1408;
constexpr int nT = nB * nS;          // 4096 tokens
constexpr int GR = nT * 2;           // 8192 gathered (token, expert) rows
constexpr int MAXTILE = 72;
constexpr int nQKV = (nNH + 2 * nNKV) * nDH;       // 3072 fused qkv width
constexpr int KOFF = nNH * nDH;                    // 2048
constexpr int VOFF = KOFF + nNKV * nDH;            // 2560
constexpr int nGU = 2 * nMI;                       // 2816 interleaved gate|up
constexpr float RMS_EPS = 1e-6f;
constexpr float QK_SCALE = 0.088388347648318447f;  // 1/sqrt(128)

// GEMM smem (half indices): 3 stages x (A 128x72 + B 128x72)
constexpr int G_HALFS = 55296;
constexpr int SMEM_BYTES = G_HALFS * 2;            // 110592

// flash smem (half indices) — R12 layout (2 CTAs/SM)
constexpr int FA_QS = 0;                 // Q  [128][136]
constexpr int FA_KS = 17408;             // K  [64][136]
constexpr int FA_VS = 26112;             // V^T 2 x [128][72]
constexpr int FA_PS = 44544;             // P  [128][72]
constexpr int FA_END = 53760;            // halfs
constexpr int FA_RMf = FA_END / 2;       // float idx: rowmax [128][2]
constexpr int FA_RLf = FA_RMf + 256;     // float idx: rowsum [128][2]
constexpr int FA_BYTES = (FA_RLf + 256) * 4;   // 109568
}

// ---------------------------------------------------------------------------
// Scratch (device globals)
// ---------------------------------------------------------------------------
__device__ __half g_xnh  [(size_t)nT * nH];
__device__ float  g_xf   [(size_t)nT * nH];
__device__ __half g_qkv  [(size_t)nT * nQKV];
__device__ __half g_vT   [(size_t)nB * nNKV * nDH * nS];
__device__ __half g_attn [(size_t)nT * nH];
__device__ float  g_hidden[(size_t)nT * nH];
__device__ __half g_x2h  [(size_t)nT * nH];
__device__ int    g_topi [nT * 2];
__device__ float  g_topw [nT * 2];
__device__ int    g_counts[nE];
__device__ int    g_fill [nE];
__device__ int    g_coff [nE + 1];
__device__ int    g_tileE[MAXTILE];
__device__ int    g_tileR0[MAXTILE];
__device__ int    g_toklist[GR];
__device__ float  g_slotw[GR];
__device__ __half g_ubuf [(size_t)GR * nMI];
// transposed weights [N][K] K-major, fp16
__device__ __half g_wqkvT[(size_t)nQKV * nH];
__device__ __half g_woT [(size_t)nH * nH];
__device__ __half g_guT [(size_t)nE * nGU * nH];
__device__ __half g_dwT [(size_t)nE * nH * nMI];

// ---------------------------------------------------------------------------
// Helpers
// ---------------------------------------------------------------------------
__device__ __forceinline__ uint32_t smem_to_u32(const void* p) {
    uint32_t a;
    asm("{ .reg .u64 t; cvta.to.shared.u64 t, %1; cvt.u32.u64 %0, t; }" : "=r"(a) : "l"(p));
    return a;
}
__device__ __forceinline__ uint32_t pack2h(float x, float y) {
    __half2 h = __floats2half2_rn(x, y);
    return *reinterpret_cast<uint32_t*>(&h);
}
__device__ __forceinline__ void mma_f16(float* d, const uint32_t* a, const uint32_t* b) {
    asm volatile("mma.sync.aligned.m16n8k16.row.col.f32.f16.f16.f32 "
        "{%0,%1,%2,%3}, {%4,%5,%6,%7}, {%8,%9}, {%0,%1,%2,%3};"
        : "+f"(d[0]), "+f"(d[1]), "+f"(d[2]), "+f"(d[3])
        : "r"(a[0]), "r"(a[1]), "r"(a[2]), "r"(a[3]), "r"(b[0]), "r"(b[1]));
}
__device__ __forceinline__ void ldsm4(uint32_t* r, uint32_t addr) {
    asm volatile("ldmatrix.sync.aligned.m8n8.x4.shared.b16 {%0,%1,%2,%3}, [%4];"
        : "=r"(r[0]), "=r"(r[1]), "=r"(r[2]), "=r"(r[3]) : "r"(addr));
}
__device__ __forceinline__ float warpSum(float v) {
    #pragma unroll
    for (int o = 16; o; o >>= 1) v += __shfl_xor_sync(0xffffffffu, v, o);
    return v;
}
__device__ __forceinline__ float siluf(float x) {
    return x * (1.f / (1.f + expf(-x)));
}

// ---------------------------------------------------------------------------
// fp16 mma GEMM with ldmatrix fragment loads (R12, byte-exact).
// ---------------------------------------------------------------------------
struct GArgs {
    const __half* A; const __half* B;
    float* Cf; __half* Ch;
    const float* resf;
    long long lda, ldb, ldc;
    int M, N, K;
    int mode;     // 0 normal, 1 moe gather-A, 2 moe no-gather
    int outHalf;
    int fuseSilu;
    int scatter;
};

__global__ void __launch_bounds__(256) tc_gemm(GArgs g) {
    extern __shared__ __half gsm[];
    const int tid = threadIdx.x, lane = tid & 31, wid = tid >> 5;
    const int wm = wid & 3, wn = wid >> 2;
    const int gq = lane >> 2, qq = lane & 3;
    const int l15 = lane & 15, lhi = lane >> 4;
    const int blr = (lane & 7) + ((lane >> 4) << 3);
    const int bco = ((lane >> 3) & 1) * 8;

    int m0, Mb;
    const __half* Ab = g.A;
    const __half* Bb = g.B;
    if (g.mode >= 1) {
        int e = g_tileE[blockIdx.y];
        if (e < 0) return;
        m0 = g_tileR0[blockIdx.y];
        Mb = g_coff[e + 1];
        Bb += (size_t)e * g.N * g.K;
    } else {
        m0 = blockIdx.y * 128;
        Mb = g.M;
    }
    const int n0 = blockIdx.x * 128;

    __shared__ int rt[128];
    if (tid < 128) {
        int m = m0 + tid;
        int r = (m < Mb) ? m : -1;
        if (g.mode == 1 && r >= 0) r = g_toklist[r];
        rt[tid] = r;
    }
    __syncthreads();

    const uint32_t sbase = smem_to_u32(gsm);
    const int NC = g.K >> 6;

    auto issue = [&](int c, int s) {
        const int k0 = c << 6;
        const uint32_t ao = (uint32_t)(s * 9216);
        const uint32_t bo = (uint32_t)(27648 + s * 9216);
        #pragma unroll
        for (int p = 0; p < 4; p++) {
            int idx = p * 256 + tid;
            int row = idx >> 3, c8 = idx & 7;
            int r = rt[row];
            const __half* src = (r >= 0 ? Ab + (size_t)r * g.lda : Ab) + k0 + c8 * 8;
            uint32_t dst = sbase + (ao + (uint32_t)(row * 72 + c8 * 8)) * 2u;
            int sz = (r >= 0) ? 16 : 0;
            asm volatile("cp.async.cg.shared.global [%0], [%1], 16, %2;"
                         :: "r"(dst), "l"(src), "r"(sz) : "memory");
        }
        #pragma unroll
        for (int p = 0; p < 4; p++) {
            int idx = p * 256 + tid;
            int row = idx >> 3, c8 = idx & 7;
            const __half* src = Bb + (size_t)(n0 + row) * g.ldb + k0 + c8 * 8;
            uint32_t dst = sbase + (bo + (uint32_t)(row * 72 + c8 * 8)) * 2u;
            asm volatile("cp.async.cg.shared.global [%0], [%1], 16, %2;"
                         :: "r"(dst), "l"(src), "r"(16) : "memory");
        }
    };

    float acc[2][8][4] = {};

    issue(0, 0);
    asm volatile("cp.async.commit_group;" ::: "memory");
    issue(1, 1);
    asm volatile("cp.async.commit_group;" ::: "memory");

    const uint32_t aLane = (uint32_t)((wm * 32 + l15) * 72 + lhi * 8);
    uint32_t bLane[4];
    #pragma unroll
    for (int p = 0; p < 4; p++)
        bLane[p] = (uint32_t)((wn * 64 + p * 16 + blr) * 72 + bco);

    for (int c = 0; c < NC; c++) {
        const int s = c % 3;
        asm volatile("cp.async.wait_group 1;" ::: "memory");
        __syncthreads();
        if (c + 2 < NC) issue(c + 2, (c + 2) % 3);
        asm volatile("cp.async.commit_group;" ::: "memory");

        const uint32_t Aad = sbase + ((uint32_t)(s * 9216) + aLane) * 2u;
        const uint32_t Bad = sbase + (uint32_t)(27648 + s * 9216) * 2u;
        #pragma unroll
        for (int kk = 0; kk < 4; kk++) {
            uint32_t af[2][4], bf[4][4];
            ldsm4(af[0], Aad + kk * 32);
            ldsm4(af[1], Aad + 16 * 144 + kk * 32);
            #pragma unroll
            for (int p = 0; p < 4; p++)
                ldsm4(bf[p], Bad + bLane[p] * 2u + kk * 32);
            #pragma unroll
            for (int mt = 0; mt < 2; mt++)
                #pragma unroll
                for (int p = 0; p < 4; p++) {
                    mma_f16(acc[mt][2 * p],     af[mt], &bf[p][0]);
                    mma_f16(acc[mt][2 * p + 1], af[mt], &bf[p][2]);
                }
        }
    }

    // Epilogue
    #pragma unroll
    for (int mt = 0; mt < 2; mt++) {
        #pragma unroll
        for (int half_ = 0; half_ < 2; half_++) {
            int r = m0 + wm * 32 + mt * 16 + half_ * 8 + gq;
            if (r >= Mb) continue;
            if (g.fuseSilu) {
                #pragma unroll
                for (int nt = 0; nt < 8; nt += 2) {
                    float g0 = acc[mt][nt][half_ * 2 + 0];
                    float g1 = acc[mt][nt][half_ * 2 + 1];
                    float u0 = acc[mt][nt + 1][half_ * 2 + 0];
                    float u1 = acc[mt][nt + 1][half_ * 2 + 1];
                    int cint = n0 + wn * 64 + nt * 8;
                    int L = ((cint) >> 4) * 8 + 2 * qq;
                    *reinterpret_cast<uint32_t*>(g.Ch + (size_t)r * g.ldc + L) =
                        pack2h(siluf(g0) * u0, siluf(g1) * u1);
                }
            } else if (g.scatter) {
                int tok = g_toklist[r];
                float w = g_slotw[r];
                float* orow = g.Cf + (size_t)tok * g.ldc;
                const int cb = n0 + wn * 64 + 2 * qq;
                #pragma unroll
                for (int nt = 0; nt < 8; nt++) {
                    atomicAdd(&orow[cb + nt * 8],     w * acc[mt][nt][half_ * 2 + 0]);
                    atomicAdd(&orow[cb + nt * 8 + 1], w * acc[mt][nt][half_ * 2 + 1]);
                }
            } else {
                const int cb = n0 + wn * 64 + 2 * qq;
                #pragma unroll
                for (int nt = 0; nt < 8; nt++) {
                    float vx = acc[mt][nt][half_ * 2 + 0];
                    float vy = acc[mt][nt][half_ * 2 + 1];
                    int col = cb + nt * 8;
                    if (g.outHalf) {
                        *reinterpret_cast<uint32_t*>(g.Ch + (size_t)r * g.ldc + col) = pack2h(vx, vy);
                    } else {
                        if (g.resf) {
                            float2 rv = *reinterpret_cast<const float2*>(g.resf + (size_t)r * g.ldc + col);
                            vx += rv.x; vy += rv.y;
                        }
                        *reinterpret_cast<float2*>(g.Cf + (size_t)r * g.ldc + col) = make_float2(vx, vy);
                    }
                }
            }
        }
    }
}

// ---------------------------------------------------------------------------
// Fused flash attention — byte-exact R12 configuration (2 CTAs/SM).
// ---------------------------------------------------------------------------
__global__ void __launch_bounds__(256) flash_kernel() {
    extern __shared__ __half fh[];
    float* ff = reinterpret_cast<float*>(fh);
    const int tid = threadIdx.x, lane = tid & 31, wid = tid >> 5;
    const int wm = wid & 3, wn = wid >> 2;
    const int gq = lane >> 2, qq = lane & 3;
    const int l15 = lane & 15, lhi = lane >> 4;
    const int blr = (lane & 7) + ((lane >> 4) << 3);
    const int bco = ((lane >> 3) & 1) * 8;
    const int bh = blockIdx.y, b = bh >> 4, h = bh & 15, kh = h >> 2;
    const int q0 = blockIdx.x * 128;

    const __half* Qg = g_qkv + ((size_t)(b * nS + q0)) * nQKV + h * nDH;
    const __half* Kg = g_qkv + (size_t)b * nS * nQKV + KOFF + kh * nDH;
    const __half* Vt = g_vT + ((size_t)(b * nNKV + kh)) * nDH * nS;
    __half* Og = g_attn + ((size_t)(b * nS + q0)) * nH + h * nDH;

    const uint32_t sb = smem_to_u32(fh);

    #pragma unroll
    for (int p = 0; p < 8; p++) {
        int idx = p * 256 + tid;
        int row = idx >> 4, c8 = idx & 15;
        uint32_t dst = sb + (uint32_t)(FA_QS + row * 136 + c8 * 8) * 2u;
        asm volatile("cp.async.cg.shared.global [%0], [%1], 16;"
                     :: "r"(dst), "l"(Qg + (size_t)row * nQKV + c8 * 8) : "memory");
    }
    asm volatile("cp.async.commit_group;" ::: "memory");

    auto issueKV = [&](int it2) {
        const __half* kg = Kg + (size_t)(it2 * 64) * nQKV;
        const __half* vg = Vt + it2 * 64;
        const int vb = FA_VS + (it2 & 1) * 9216;
        #pragma unroll
        for (int p = 0; p < 4; p++) {
            int idx = p * 256 + tid;
            int row = idx >> 4, c8 = idx & 15;
            uint32_t dk = sb + (uint32_t)(FA_KS + row * 136 + c8 * 8) * 2u;
            asm volatile("cp.async.cg.shared.global [%0], [%1], 16;"
                         :: "r"(dk), "l"(kg + (size_t)row * nQKV + c8 * 8) : "memory");
        }
        #pragma unroll
        for (int p = 0; p < 4; p++) {
            int idx = p * 256 + tid;
            int row = idx >> 3, c8 = idx & 7;
            uint32_t dv = sb + (uint32_t)(vb + row * 72 + c8 * 8) * 2u;
            asm volatile("cp.async.cg.shared.global [%0], [%1], 16;"
                         :: "r"(dv), "l"(vg + (size_t)row * nS + c8 * 8) : "memory");
        }
    };
    issueKV(0);
    asm volatile("cp.async.commit_group;" ::: "memory");

    float accO[2][8][4] = {};
    float rm[2][2] = {{-1e30f, -1e30f}, {-1e30f, -1e30f}};
    float rl[2][2] = {{0.f, 0.f}, {0.f, 0.f}};
    const int PSu = FA_PS / 2;

    const uint32_t QA = sb + (uint32_t)(FA_QS + (wm * 32 + l15) * 136 + lhi * 8) * 2u;
    uint32_t KB[2];
    #pragma unroll
    for (int p = 0; p < 2; p++)
        KB[p] = sb + (uint32_t)(FA_KS + (wn * 32 + p * 16 + blr) * 136 + bco) * 2u;
    const uint32_t PA = sb + (uint32_t)(FA_PS + (wm * 32 + l15) * 72 + lhi * 8) * 2u;
    uint32_t VBl[4];
    #pragma unroll
    for (int p = 0; p < 4; p++)
        VBl[p] = (uint32_t)((wn * 64 + p * 16 + blr) * 72 + bco) * 2u;

    for (int it = 0; it < nS / 64; it++) {
        asm volatile("cp.async.wait_group 0;" ::: "memory");
        __syncthreads();

        // --- S = Q x K^T ---
        float S[2][4][4] = {};
        #pragma unroll
        for (int kc = 0; kc < 8; kc++) {
            uint32_t af[2][4], bf[2][4];
            ldsm4(af[0], QA + kc * 32);
            ldsm4(af[1], QA + 16 * 272 + kc * 32);
            ldsm4(bf[0], KB[0] + kc * 32);
            ldsm4(bf[1], KB[1] + kc * 32);
            #pragma unroll
            for (int mt = 0; mt < 2; mt++)
                #pragma unroll
                for (int p = 0; p < 2; p++) {
                    mma_f16(S[mt][2 * p],     af[mt], &bf[p][0]);
                    mma_f16(S[mt][2 * p + 1], af[mt], &bf[p][2]);
                }
        }
        __syncthreads();
        if (it + 1 < nS / 64) issueKV(it + 1);
        asm volatile("cp.async.commit_group;" ::: "memory");

        float tmax[2][2] = {{-1e30f, -1e30f}, {-1e30f, -1e30f}};
        #pragma unroll
        for (int mt = 0; mt < 2; mt++)
            #pragma unroll
            for (int nt = 0; nt < 4; nt++)
                #pragma unroll
                for (int c = 0; c < 4; c++) {
                    S[mt][nt][c] *= QK_SCALE;
                    tmax[mt][c >> 1] = fmaxf(tmax[mt][c >> 1], S[mt][nt][c]);
                }
        #pragma unroll
        for (int mt = 0; mt < 2; mt++)
            #pragma unroll
            for (int hf = 0; hf < 2; hf++) {
                float v = tmax[mt][hf];
                v = fmaxf(v, __shfl_xor_sync(0xffffffffu, v, 1));
                v = fmaxf(v, __shfl_xor_sync(0xffffffffu, v, 2));
                tmax[mt][hf] = v;
            }
        if (qq == 0) {
            #pragma unroll
            for (int mt = 0; mt < 2; mt++)
                #pragma unroll
                for (int hf = 0; hf < 2; hf++)
                    ff[FA_RMf + (wm * 32 + mt * 16 + hf * 8 + gq) * 2 + wn] = tmax[mt][hf];
        }
        __syncthreads();

        float newm[2][2], sco[2][2];
        #pragma unroll
        for (int mt = 0; mt < 2; mt++)
            #pragma unroll
            for (int hf = 0; hf < 2; hf++) {
                int r = wm * 32 + mt * 16 + hf * 8 + gq;
                float tm = fmaxf(ff[FA_RMf + r * 2], ff[FA_RMf + r * 2 + 1]);
                float nm = fmaxf(rm[mt][hf], tm);
                sco[mt][hf] = __expf(rm[mt][hf] - nm);
                newm[mt][hf] = nm;
                rm[mt][hf] = nm;
            }

        float ps[2][2] = {{0.f, 0.f}, {0.f, 0.f}};
        uint32_t* Pw = reinterpret_cast<uint32_t*>(fh);
        #pragma unroll
        for (int mt = 0; mt < 2; mt++) {
            int r0 = wm * 32 + mt * 16 + gq;
            #pragma unroll
            for (int nt = 0; nt < 4; nt++) {
                int ci = wn * 16 + nt * 4 + qq;
                float p0 = __expf(S[mt][nt][0] - newm[mt][0]);
                float p1 = __expf(S[mt][nt][1] - newm[mt][0]);
                float p2 = __expf(S[mt][nt][2] - newm[mt][1]);
                float p3 = __expf(S[mt][nt][3] - newm[mt][1]);
                ps[mt][0] += p0 + p1;
                ps[mt][1] += p2 + p3;
                Pw[PSu + r0 * 36 + ci] = pack2h(p0, p1);
                Pw[PSu + (r0 + 8) * 36 + ci] = pack2h(p2, p3);
            }
        }
        #pragma unroll
        for (int mt = 0; mt < 2; mt++)
            #pragma unroll
            for (int hf = 0; hf < 2; hf++) {
                float v = ps[mt][hf];
                v += __shfl_xor_sync(0xffffffffu, v, 1);
                v += __shfl_xor_sync(0xffffffffu, v, 2);
                ps[mt][hf] = v;
            }
        if (qq == 0) {
            #pragma unroll
            for (int mt = 0; mt < 2; mt++)
                #pragma unroll
                for (int hf = 0; hf < 2; hf++)
                    ff[FA_RLf + (wm * 32 + mt * 16 + hf * 8 + gq) * 2 + wn] = ps[mt][hf];
        }
        __syncthreads();

        #pragma unroll
        for (int mt = 0; mt < 2; mt++)
            #pragma unroll
            for (int hf = 0; hf < 2; hf++) {
                int r = wm * 32 + mt * 16 + hf * 8 + gq;
                float ts = ff[FA_RLf + r * 2] + ff[FA_RLf + r * 2 + 1];
                rl[mt][hf] = rl[mt][hf] * sco[mt][hf] + ts;
            }
        #pragma unroll
        for (int mt = 0; mt < 2; mt++)
            #pragma unroll
            for (int nt = 0; nt < 8; nt++) {
                accO[mt][nt][0] *= sco[mt][0];
                accO[mt][nt][1] *= sco[mt][0];
                accO[mt][nt][2] *= sco[mt][1];
                accO[mt][nt][3] *= sco[mt][1];
            }

        // --- O += P x V ---
        const uint32_t Vad = sb + (uint32_t)(FA_VS + (it & 1) * 9216) * 2u;
        #pragma unroll
        for (int kc = 0; kc < 4; kc++) {
            uint32_t af[2][4], bf[4][4];
            ldsm4(af[0], PA + kc * 32);
            ldsm4(af[1], PA + 16 * 144 + kc * 32);
            #pragma unroll
            for (int p = 0; p < 4; p++)
                ldsm4(bf[p], Vad + VBl[p] + kc * 32);
            #pragma unroll
            for (int mt = 0; mt < 2; mt++)
                #pragma unroll
                for (int p = 0; p < 4; p++) {
                    mma_f16(accO[mt][2 * p],     af[mt], &bf[p][0]);
                    mma_f16(accO[mt][2 * p + 1], af[mt], &bf[p][2]);
                }
        }
    }

    #pragma unroll
    for (int mt = 0; mt < 2; mt++)
        #pragma unroll
        for (int hf = 0; hf < 2; hf++) {
            int r = wm * 32 + mt * 16 + hf * 8 + gq;
            float inv = 1.f / rl[mt][hf];
            #pragma unroll
            for (int nt = 0; nt < 8; nt++) {
                int col = wn * 64 + nt * 8 + 2 * qq;
                *reinterpret_cast<uint32_t*>(Og + (size_t)r * nH + col) =
                    pack2h(accO[mt][nt][hf * 2 + 0] * inv, accO[mt][nt][hf * 2 + 1] * inv);
            }
        }
}

// ---------------------------------------------------------------------------
// Weight transpose fp32->fp16, 64k x 128n tile, optional gate/up interleave.
// ---------------------------------------------------------------------------
__global__ void __launch_bounds__(256) transpose_kernel(
    const float* __restrict__ in, __half* __restrict__ out, int K, int N,
    long long srcZ, long long dstZ, int remapOfs) {
    __shared__ float t[64][137];
    const float* ip = in + (size_t)blockIdx.z * srcZ;
    __half* op = out + (size_t)blockIdx.z * dstZ;
    const int n0 = blockIdx.x * 128, k0 = blockIdx.y * 64;
    const int tid = threadIdx.x;
    const int rr = tid >> 5, rc = tid & 31;
    #pragma unroll
    for (int p = 0; p < 8; p++) {
        int kk = rr + p * 8;
        float4 v = *reinterpret_cast<const float4*>(ip + (size_t)(k0 + kk) * N + n0 + rc * 4);
        t[kk][rc * 4 + 0] = v.x; t[kk][rc * 4 + 1] = v.y;
        t[kk][rc * 4 + 2] = v.z; t[kk][rc * 4 + 3] = v.w;
    }
    __syncthreads();
    const int wr = tid >> 3, wk8 = (tid & 7) * 8;
    #pragma unroll
    for (int p = 0; p < 4; p++) {
        int nn = wr + p * 32;
        int ng = n0 + nn;
        int nd = (remapOfs < 0) ? ng : ((ng >> 3) << 4) + (ng & 7) + remapOfs;
        __half hv[8];
        #pragma unroll
        for (int j = 0; j < 8; j++) hv[j] = __float2half_rn(t[wk8 + j][nn]);
        *reinterpret_cast<uint4*>(op + (size_t)nd * K + k0 + wk8) =
            *reinterpret_cast<uint4*>(hv);
    }
}

// V transpose (half): g_qkv v-section -> g_vT [(b*4+kh)][dh][S]
__global__ void vtrans_kernel() {
    __shared__ __half t[32][33];
    int z = blockIdx.z, b = z >> 2, kh = z & 3;
    int s0 = blockIdx.x * 32, d0 = blockIdx.y * 32;
    int tx = threadIdx.x & 31, ty = threadIdx.x >> 5;
    #pragma unroll
    for (int i = ty; i < 32; i += 8)
        t[i][tx] = g_qkv[((size_t)(b * nS + s0 + i)) * nQKV + VOFF + kh * nDH + d0 + tx];
    __syncthreads();
    #pragma unroll
    for (int i = ty; i < 32; i += 8)
        g_vT[((size_t)z * nDH + d0 + i) * nS + s0 + tx] = t[tx][i];
}

// ---------------------------------------------------------------------------
// RMSNorm. rmsnorm1 -> half. rmsnorm2 -> half + float (router) + out init.
// ---------------------------------------------------------------------------
template <bool DUAL>
__device__ __forceinline__ void rmsnorm_row(const float* __restrict__ x,
                                            const float* __restrict__ w,
                                            __half* __restrict__ out_h,
                                            float* __restrict__ out_f,
                                            float* __restrict__ out_cp) {
    int row = blockIdx.x;
    const float* xr = x + (size_t)row * nH;
    float ss = 0.f;
    for (int i = threadIdx.x; i < nH; i += blockDim.x) { float v = xr[i]; ss += v * v; }
    __shared__ float sm[8];
    int lane = threadIdx.x & 31, wid = threadIdx.x >> 5;
    ss = warpSum(ss);
    if (lane == 0) sm[wid] = ss;
    __syncthreads();
    if (wid == 0) {
        float v = (lane < 8) ? sm[lane] : 0.f;
        v = warpSum(v);
        if (lane == 0) sm[0] = rsqrtf(v / (float)nH + RMS_EPS);
    }
    __syncthreads();
    float inv = sm[0];
    for (int i = threadIdx.x; i < nH; i += blockDim.x) {
        float xi = xr[i];
        float v = xi * inv * w[i];
        out_h[(size_t)row * nH + i] = __float2half_rn(v);
        if (DUAL) {
            out_f[(size_t)row * nH + i] = v;
            out_cp[(size_t)row * nH + i] = xi;
        }
    }
}
__global__ void rmsnorm1_kernel(const float* __restrict__ hs, const float* __restrict__ w) {
    rmsnorm_row<false>(hs, w, g_xnh, nullptr, nullptr);
}
__global__ void rmsnorm2_kernel(const float* __restrict__ w, float* __restrict__ out) {
    rmsnorm_row<true>(g_hidden, w, g_x2h, g_xf, out);
}

// ---------------------------------------------------------------------------
// RoPE on fused qkv, vectorized half2 (fp32 math per element, bit-identical).
// Each thread handles 2 consecutive d values in both halves of the rotation.
// ---------------------------------------------------------------------------
__global__ void rope_kernel(const float* __restrict__ cosb, const float* __restrict__ sinb) {
    int i = blockIdx.x * blockDim.x + threadIdx.x;
    if (i >= nT * (nNH + nNKV) * 32) return;
    int d  = (i & 31) * 2;
    int hh = (i >> 5) % (nNH + nNKV);
    int t  = i / (32 * (nNH + nNKV));
    __half* ptr = g_qkv + (size_t)t * nQKV +
                  (hh < nNH ? hh * nDH : KOFF + (hh - nNH) * nDH);
    __half2 lo = *reinterpret_cast<__half2*>(ptr + d);
    __half2 hi = *reinterpret_cast<__half2*>(ptr + d + 64);
    float x1a = __half2float(__low2half(lo)),  x1b = __half2float(__high2half(lo));
    float x2a = __half2float(__low2half(hi)),  x2b = __half2float(__high2half(hi));
    const float* cr = cosb + (size_t)t * nDH;
    const float* sr = sinb + (size_t)t * nDH;
    float c0 = cr[d], c1 = cr[d + 1], c64 = cr[d + 64], c65 = cr[d + 65];
    float s0 = sr[d], s1 = sr[d + 1], s64 = sr[d + 64], s65 = sr[d + 65];
    __half2 olo = __floats2half2_rn(x1a * c0 - x2a * s0, x1b * c1 - x2b * s1);
    __half2 ohi = __floats2half2_rn(x2a * c64 + x1a * s64, x2b * c65 + x1b * s65);
    *reinterpret_cast<__half2*>(ptr + d) = olo;
    *reinterpret_cast<__half2*>(ptr + d + 64) = ohi;
}

// ---------------------------------------------------------------------------
// Router (UNROUNDED fp32 input)
// ---------------------------------------------------------------------------
__global__ void router_kernel(const float* __restrict__ rw) {
    __shared__ float xs[nH];
    __shared__ float lg[nE];
    int t = blockIdx.x;
    for (int i = threadIdx.x; i < nH; i += blockDim.x) xs[i] = g_xf[(size_t)t * nH + i];
    __syncthreads();
    int w = threadIdx.x >> 5, lane = threadIdx.x & 31;
    float s = 0.f;
    for (int i = lane; i < nH; i += 32) s += xs[i] * rw[(size_t)i * nE + w];
    s = warpSum(s);
    if (lane == 0) lg[w] = s;
    __syncthreads();
    if (threadIdx.x == 0) {
        float mx = lg[0];
        #pragma unroll
        for (int e = 1; e < nE; e++) mx = fmaxf(mx, lg[e]);
        float p[nE]; float sum = 0.f;
        #pragma unroll
        for (int e = 0; e < nE; e++) { p[e] = expf(lg[e] - mx); sum += p[e]; }
        #pragma unroll
        for (int e = 0; e < nE; e++) p[e] /= sum;
        int i1 = 0;
        #pragma unroll
        for (int e = 1; e < nE; e++) if (p[e] > p[i1]) i1 = e;
        int i2 = (i1 == 0) ? 1 : 0;
        #pragma unroll
        for (int e = 0; e < nE; e++) if (e != i1 && p[e] > p[i2]) i2 = e;
        float s2 = p[i1] + p[i2];
        g_topi[t * 2] = i1; g_topi[t * 2 + 1] = i2;
        g_topw[t * 2] = p[i1] / s2; g_topw[t * 2 + 1] = p[i2] / s2;
    }
}

// ---------------------------------------------------------------------------
// MoE bookkeeping. scan_kernel zeroes g_counts after use (next graph replay
// starts clean; device globals are zero-initialized for the first run).
// ---------------------------------------------------------------------------
__global__ void count_kernel() {
    int t = blockIdx.x * blockDim.x + threadIdx.x;
    if (t >= nT) return;
    atomicAdd(&g_counts[g_topi[t * 2]], 1);
    atomicAdd(&g_counts[g_topi[t * 2 + 1]], 1);
}
__global__ void scan_kernel() {
    if (threadIdx.x != 0) return;
    int off = 0, nt_ = 0;
    for (int e = 0; e < nE; e++) {
        g_coff[e] = off;
        g_fill[e] = 0;
        int ne = g_counts[e];
        g_counts[e] = 0;                       // reset for next replay
        int ntl = (ne + 127) >> 7;
        for (int i = 0; i < ntl; i++) { g_tileE[nt_] = e; g_tileR0[nt_] = off + i * 128; nt_++; }
        off += ne;
    }
    g_coff[nE] = off;
    for (int i = nt_; i < MAXTILE; i++) g_tileE[i] = -1;
}
__global__ void scatter_kernel() {
    int t = blockIdx.x * blockDim.x + threadIdx.x;
    if (t >= nT) return;
    #pragma unroll
    for (int k = 0; k < 2; k++) {
        int e = g_topi[t * 2 + k];
        int pos = g_coff[e] + atomicAdd(&g_fill[e], 1);
        g_toklist[pos] = t;
        g_slotw[pos] = g_topw[t * 2 + k];
    }
}

// ---------------------------------------------------------------------------
// Launch
// ---------------------------------------------------------------------------
static void launch_gemm(const __half* A, long long lda, const __half* B, long long ldb,
                        float* Cf, __half* Ch, long long ldc, const float* resf,
                        int M, int N, int K, int mode, int outHalf, int fuseSilu,
                        int scatter, dim3 grid) {
    GArgs g;
    g.A = A; g.B = B; g.Cf = Cf; g.Ch = Ch; g.resf = resf;
    g.lda = lda; g.ldb = ldb; g.ldc = ldc;
    g.M = M; g.N = N; g.K = K;
    g.mode = mode; g.outHalf = outHalf; g.fuseSilu = fuseSilu; g.scatter = scatter;
    tc_gemm<<<grid, 256, SMEM_BYTES>>>(g);
}

extern "C" void kernel_launch(void* const* d_in, const int* in_sizes, int n_in,
                              void* d_out, int out_size) {
    const float* hs   = (const float*)d_in[0];
    const float* cosb = (const float*)d_in[1];
    const float* sinb = (const float*)d_in[2];
    const float* wq   = (const float*)d_in[3];
    const float* wk   = (const float*)d_in[4];
    const float* wv   = (const float*)d_in[5];
    const float* wo   = (const float*)d_in[6];
    const float* ln1  = (const float*)d_in[7];
    const float* ln2  = (const float*)d_in[8];
    const float* rw   = (const float*)d_in[9];
    const float* gw   = (const float*)d_in[10];
    const float* uw   = (const float*)d_in[11];
    const float* dw   = (const float*)d_in[12];
    float* out = (float*)d_out;

    static bool attr_set = false;
    if (!attr_set) {
        cudaFuncSetAttribute(tc_gemm, cudaFuncAttributeMaxDynamicSharedMemorySize, SMEM_BYTES);
        cudaFuncSetAttribute(flash_kernel, cudaFuncAttributeMaxDynamicSharedMemorySize, FA_BYTES);
        attr_set = true;
    }

    __half* wqkvT; cudaGetSymbolAddress((void**)&wqkvT, g_wqkvT);
    __half* woT; cudaGetSymbolAddress((void**)&woT, g_woT);
    __half* guT; cudaGetSymbolAddress((void**)&guT, g_guT);
    __half* dwT; cudaGetSymbolAddress((void**)&dwT, g_dwT);
    __half* xnh; cudaGetSymbolAddress((void**)&xnh, g_xnh);
    __half* qkv; cudaGetSymbolAddress((void**)&qkv, g_qkv);
    __half* at;  cudaGetSymbolAddress((void**)&at, g_attn);
    float*  hid; cudaGetSymbolAddress((void**)&hid, g_hidden);
    __half* x2h; cudaGetSymbolAddress((void**)&x2h, g_x2h);
    __half* ub;  cudaGetSymbolAddress((void**)&ub, g_ubuf);

    // Weight transposes -> [N][K] fp16
    transpose_kernel<<<dim3(16, 32, 1), 256>>>(wq, wqkvT, nH, nNH * nDH, 0, 0, -1);
    transpose_kernel<<<dim3(4, 32, 1), 256>>>(wk, wqkvT + (size_t)KOFF * nH, nH, nNKV * nDH, 0, 0, -1);
    transpose_kernel<<<dim3(4, 32, 1), 256>>>(wv, wqkvT + (size_t)VOFF * nH, nH, nNKV * nDH, 0, 0, -1);
    transpose_kernel<<<dim3(16, 32, 1), 256>>>(wo, woT, nH, nH, 0, 0, -1);
    transpose_kernel<<<dim3(11, 32, nE), 256>>>(gw, guT, nH, nMI,
        (long long)nH * nMI, (long long)nGU * nH, 0);
    transpose_kernel<<<dim3(11, 32, nE), 256>>>(uw, guT, nH, nMI,
        (long long)nH * nMI, (long long)nGU * nH, 8);
    transpose_kernel<<<dim3(16, 22, nE), 256>>>(dw, dwT, nMI, nH,
        (long long)nMI * nH, (long long)nMI * nH, -1);

    rmsnorm1_kernel<<<nT, 256>>>(hs, ln1);

    // Fused QKV projection (half out, N=3072)
    launch_gemm(xnh, nH, wqkvT, nH, nullptr, qkv, nQKV, nullptr,
                nT, nQKV, nH, 0, 1, 0, 0, dim3(24, 32, 1));

    rope_kernel<<<(nT * (nNH + nNKV) * 32) / 256, 256>>>(cosb, sinb);
    vtrans_kernel<<<dim3(nS / 32, nDH / 32, nB * nNKV), 256>>>();

    // fused attention
    flash_kernel<<<dim3(nS / 128, nB * nNH), 256, FA_BYTES>>>();

    // hidden = attn @ wo + residual (fp32)
    launch_gemm(at, nH, woT, nH, hid, nullptr, nH, hs,
                nT, nH, nH, 0, 0, 0, 0, dim3(16, 32, 1));

    rmsnorm2_kernel<<<nT, 256>>>(ln2, out);   // also: out = hidden
    router_kernel<<<nT, 256>>>(rw);

    count_kernel<<<nT / 256, 256>>>();
    scan_kernel<<<1, 1>>>();
    scatter_kernel<<<nT / 256, 256>>>();

    // MoE: fused gate+up (interleaved, silu in epilogue) -> ubuf (half)
    launch_gemm(x2h, nH, guT, nH, nullptr, ub, nMI, nullptr,
                GR, nGU, nH, 1, 0, 1, 0, dim3(22, MAXTILE, 1));
    // down: scatter-add into out
    launch_gemm(ub, nMI, dwT, nMI, out, nullptr, nH, nullptr,
                GR, nH, nMI, 2, 0, 0, 1, dim3(16, MAXTILE, 1));
}